// round 15
// baseline (speedup 1.0000x reference)
#include <cuda_runtime.h>
#include <cuda_bf16.h>

// Problem constants
#define Bc 2
#define Nc 96
#define NNc 9216            // Nc*Nc
#define Dc 64
#define Hc 4
#define DKc 16
#define ROWS_TOTAL 18432    // Bc*NNc

// Scratch (device globals; allocation-free per harness rules)
// g_proj layout: [proj(4)][b(2)][h(4)][i(9216)][d(16)]  (proj==1 slot unused)
__device__ float g_proj[4u * Bc * Hc * NNc * DKc];          // 18.9 MB
// rk transposed: [b][h][a(96)][d(16)][y(96)]
__device__ float g_rkT[(size_t)Bc * Hc * Nc * DKc * Nc];    // 4.7 MB
__device__ float g_attout[(size_t)ROWS_TOTAL * Dc];         // 4.7 MB

// ---------------------------------------------------------------------------
// Kernel A: projection.  128 threads, TWO 32-row tiles per block (weights
// loaded once, prologue amortized).  4x4 per-thread tile.  proj==1 tiles
// transposed through the st_s buffer and written to g_rkT coalesced.
// smem ~27 KB, regs 64 -> 8 blocks/SM, grid 1152 -> single wave.
// ---------------------------------------------------------------------------
#define A_WS_STRIDE 68
#define T_STRIDE 36          // transpose staging stride (64 x 36 <= st_s)

__global__ void __launch_bounds__(128)
proj_kernel(const float* __restrict__ state,
            const float* __restrict__ w_lk, const float* __restrict__ b_lk,
            const float* __restrict__ w_rk, const float* __restrict__ b_rk,
            const float* __restrict__ w_lv, const float* __restrict__ b_lv,
            const float* __restrict__ w_rv, const float* __restrict__ b_rv)
{
    __shared__ __align__(16) float w_s[64 * A_WS_STRIDE];   // 17.4 KB
    __shared__ __align__(16) float st_s[64 * T_STRIDE];     // 9.2 KB (state / transpose)
    __shared__ float bias_s[64];

    const int tid = threadIdx.x;
    const int proj = blockIdx.y;

    const float* W = (proj == 0) ? w_lk : (proj == 1) ? w_rk
                    : (proj == 2) ? w_lv : w_rv;
    const float* Bv = (proj == 0) ? b_lk : (proj == 1) ? b_rk
                     : (proj == 2) ? b_lv : b_rv;

    for (int idx = tid; idx < 4096; idx += 128) {
        int p = idx >> 6, k = idx & 63;
        w_s[k * A_WS_STRIDE + p] = W[idx];
    }
    if (tid < 64) bias_s[tid] = Bv[tid];

    const int p0 = (tid & 15) * 4;
    const int r0 = (tid >> 4) * 4;
    const float4 bv4 = *(const float4*)&Bv[p0];   // bias via LDG (tiny, cached)

#pragma unroll
    for (int t = 0; t < 2; ++t) {
        const int rowBase = blockIdx.x * 64 + t * 32;

        if (t) __syncthreads();          // previous tile's st_s reads done
        {
            const float4* src = (const float4*)(state + (size_t)rowBase * 64);
            float4* dst = (float4*)st_s;
#pragma unroll
            for (int i = 0; i < 4; ++i) dst[tid + i * 128] = src[tid + i * 128];
        }
        __syncthreads();

        float acc[4][4];
#pragma unroll
        for (int i = 0; i < 4; ++i)
#pragma unroll
            for (int j = 0; j < 4; ++j) acc[i][j] = 0.f;

#pragma unroll 8
        for (int k = 0; k < 64; ++k) {
            float4 wv = *(const float4*)&w_s[k * A_WS_STRIDE + p0];
#pragma unroll
            for (int i = 0; i < 4; ++i) {
                float s = st_s[(r0 + i) * 64 + k];
                acc[i][0] += s * wv.x;
                acc[i][1] += s * wv.y;
                acc[i][2] += s * wv.z;
                acc[i][3] += s * wv.w;
            }
        }

        const int b   = rowBase / NNc;
        const int idx0 = rowBase - b * NNc;

        if (proj == 1) {
            // ---- transpose through st_s, write g_rkT[b][h][a][d][y] coalesced
            __syncthreads();             // all FMA reads of st_s done
#pragma unroll
            for (int i = 0; i < 4; ++i) {
                st_s[(p0 + 0) * T_STRIDE + r0 + i] = acc[i][0] + bv4.x;
                st_s[(p0 + 1) * T_STRIDE + r0 + i] = acc[i][1] + bv4.y;
                st_s[(p0 + 2) * T_STRIDE + r0 + i] = acc[i][2] + bv4.z;
                st_s[(p0 + 3) * T_STRIDE + r0 + i] = acc[i][3] + bv4.w;
            }
            __syncthreads();

            const int a  = idx0 / 96;
            const int y0 = idx0 - a * 96;
#pragma unroll
            for (int r = 0; r < 4; ++r) {
                int ii = tid + r * 128;      // 512 float4 total
                int p  = ii >> 3;            // 0..63  (h,d)
                int yq = ii & 7;             // 0..7
                float4 v = *(const float4*)&st_s[p * T_STRIDE + yq * 4];
                int h = p >> 4, d = p & 15;
                size_t off = ((((size_t)(b * Hc + h) * Nc + a) * DKc + d) * Nc)
                           + y0 + yq * 4;
                *(float4*)&g_rkT[off] = v;
            }
        } else {
            const int h  = p0 >> 4;
            const int d0 = p0 & 15;
#pragma unroll
            for (int i = 0; i < 4; ++i) {
                int idx = idx0 + r0 + i;
                float4 v;
                v.x = acc[i][0] + bv4.x;
                v.y = acc[i][1] + bv4.y;
                v.z = acc[i][2] + bv4.z;
                v.w = acc[i][3] + bv4.w;
                size_t off = ((size_t)((proj * Bc + b) * Hc + h) * NNc + idx) * DKc + d0;
                *(float4*)&g_proj[off] = v;
            }
        }
    }
}

// ---------------------------------------------------------------------------
// Kernel B: streaming edge-attention, no-max softmax (R12/R14 proven, ACH=24).
// ---------------------------------------------------------------------------
#define TXB 6
#define YB  32
#define ACH 24
#define CF4 (TXB * ACH * DKc / 4)   // 576 float4 per lk/lv chunk

__global__ void __launch_bounds__(384, 3)
attn_kernel()
{
    __shared__ __align__(16) float lk_s[TXB * ACH * DKc];   // 2304
    __shared__ __align__(16) float lv_s[TXB * ACH * DKc];   // 2304
    __shared__ __align__(16) float sc_s[TXB * ACH * YB];    // 4608
    float* part = lk_s;
    float* pden = sc_s + 1024;

    const int tid = threadIdx.x;
    const int yt = blockIdx.x % 3;
    const int xt = (blockIdx.x / 3) & 15;
    const int bh = blockIdx.x / 48;
    const int h  = bh % Hc;
    const int b  = bh / Hc;
    const int x0 = xt * TXB;
    const int yb = yt * YB;

    const int slab = NNc * DKc;  // 147456
    const float* lkbase = g_proj + (size_t)((0 * Bc + b) * Hc + h) * slab;
    const float* lvbase = g_proj + (size_t)((2 * Bc + b) * Hc + h) * slab;
    const float* rvbase = g_proj + (size_t)((3 * Bc + b) * Hc + h) * slab;
    const float* rkT    = g_rkT + (size_t)(b * Hc + h) * Nc * DKc * Nc;

    const int wA = tid >> 5;          // 0..11
    const int lA = tid & 31;          // y-lane
    const int as = tid >> 7;          // 0..2
    const int rr = tid & 127;
    const int yl = rr >> 2;           // 0..31
    const int dq = rr & 3;            // 0..3
    const int y  = yb + yl;

    float4 num[TXB];
    float  den[TXB];
#pragma unroll
    for (int t = 0; t < TXB; ++t) { num[t] = make_float4(0,0,0,0); den[t] = 0.f; }

    for (int a0 = 0; a0 < 96; a0 += ACH) {
        __syncthreads();

        for (int i = tid; i < 2 * CF4; i += 384) {
            int arr = i >= CF4;
            int j   = arr ? i - CF4 : i;
            int tx  = j / (ACH * DKc / 4);
            int k   = j - tx * (ACH * DKc / 4);
            const float* src = (arr ? lvbase : lkbase)
                             + (size_t)((x0 + tx) * 96 + a0) * DKc;
            float* dst = (arr ? lv_s : lk_s) + tx * (ACH * DKc);
            ((float4*)dst)[k] = ((const float4*)src)[k];
        }
        __syncthreads();

#pragma unroll
        for (int rep = 0; rep < 2; ++rep) {
            const int al = wA + rep * 12;
            const int a  = a0 + al;
            const float* rkp = rkT + ((size_t)a * DKc) * Nc + yb + lA;
            float ps[TXB];
            {
                float r[8];
#pragma unroll
                for (int d = 0; d < 8; ++d) r[d] = rkp[(size_t)d * Nc];
#pragma unroll
                for (int tx = 0; tx < TXB; ++tx) {
                    const float4* lp = (const float4*)(lk_s + (tx * ACH + al) * DKc);
                    float4 l0 = lp[0], l1 = lp[1];
                    ps[tx] = l0.x * r[0] + l0.y * r[1] + l0.z * r[2] + l0.w * r[3]
                           + l1.x * r[4] + l1.y * r[5] + l1.z * r[6] + l1.w * r[7];
                }
            }
            {
                float r[8];
#pragma unroll
                for (int d = 0; d < 8; ++d) r[d] = rkp[(size_t)(8 + d) * Nc];
#pragma unroll
                for (int tx = 0; tx < TXB; ++tx) {
                    const float4* lp = (const float4*)(lk_s + (tx * ACH + al) * DKc + 8);
                    float4 l2 = lp[0], l3 = lp[1];
                    float s = ps[tx]
                            + l2.x * r[0] + l2.y * r[1] + l2.z * r[2] + l2.w * r[3]
                            + l3.x * r[4] + l3.y * r[5] + l3.z * r[6] + l3.w * r[7];
                    sc_s[(tx * ACH + al) * YB + lA] = __expf(s * 0.25f);
                }
            }
        }
        __syncthreads();

#pragma unroll
        for (int j = 0; j < 8; ++j) {
            const int al = as * 8 + j;
            const int a  = a0 + al;
            float4 rv = *(const float4*)(rvbase + ((size_t)(a * 96 + y)) * DKc + dq * 4);
#pragma unroll
            for (int tx = 0; tx < TXB; ++tx) {
                float e = sc_s[(tx * ACH + al) * YB + yl];
                float4 v = *(const float4*)(lv_s + (tx * ACH + al) * DKc + dq * 4);
                num[tx].x += e * (v.x * rv.x);
                num[tx].y += e * (v.y * rv.y);
                num[tx].z += e * (v.z * rv.z);
                num[tx].w += e * (v.w * rv.w);
                den[tx]   += e;
            }
        }
    }

    __syncthreads();
#pragma unroll
    for (int step = 0; step < 3; ++step) {
        if (as == step) {
            float4* p4 = (float4*)part;
            if (step == 0) {
#pragma unroll
                for (int tx = 0; tx < TXB; ++tx) {
                    p4[(tx * YB + yl) * 4 + dq] = num[tx];
                    if (dq == 0) pden[tx * YB + yl] = den[tx];
                }
            } else {
#pragma unroll
                for (int tx = 0; tx < TXB; ++tx) {
                    float4 c = p4[(tx * YB + yl) * 4 + dq];
                    c.x += num[tx].x; c.y += num[tx].y;
                    c.z += num[tx].z; c.w += num[tx].w;
                    p4[(tx * YB + yl) * 4 + dq] = c;
                    if (dq == 0) pden[tx * YB + yl] += den[tx];
                }
            }
        }
        __syncthreads();
    }

    {
        const float4* p4 = (const float4*)part;
#pragma unroll
        for (int r = 0; r < 2; ++r) {
            int idx = tid + r * 384;
            int dqo = idx & 3;
            int cyl = (idx >> 2) & 31;
            int tx  = idx >> 7;
            float inv = 1.f / pden[tx * YB + cyl];
            float4 o = p4[idx];
            o.x *= inv; o.y *= inv; o.z *= inv; o.w *= inv;
            size_t row = (size_t)b * NNc + (size_t)(x0 + tx) * 96 + (yb + cyl);
            *(float4*)&g_attout[row * 64 + h * 16 + dqo * 4] = o;
        }
    }
}

// ---------------------------------------------------------------------------
// Kernel C: output projection (R14: 16 rows x 64 cols, 64 threads, 4x4 tile).
// ---------------------------------------------------------------------------
__global__ void __launch_bounds__(64)
out_kernel(const float* __restrict__ w_out, const float* __restrict__ b_out,
           float* __restrict__ out)
{
    __shared__ __align__(16) float w_s[64 * A_WS_STRIDE];
    __shared__ __align__(16) float st_s[16 * 64];
    __shared__ float bias_s[64];

    const int tid = threadIdx.x;
    const int rowBase = blockIdx.x * 16;

    for (int idx = tid; idx < 4096; idx += 64) {
        int p = idx >> 6, k = idx & 63;
        w_s[k * A_WS_STRIDE + p] = w_out[idx];
    }
    if (tid < 64) bias_s[tid] = b_out[tid];
    {
        const float4* src = (const float4*)(g_attout + (size_t)rowBase * 64);
        float4* dst = (float4*)st_s;
#pragma unroll
        for (int i = 0; i < 4; ++i) dst[tid + i * 64] = src[tid + i * 64];
    }
    __syncthreads();

    const int p0 = (tid & 15) * 4;
    const int r0 = (tid >> 4) * 4;

    float acc[4][4];
#pragma unroll
    for (int i = 0; i < 4; ++i)
#pragma unroll
        for (int j = 0; j < 4; ++j) acc[i][j] = 0.f;

#pragma unroll 8
    for (int k = 0; k < 64; ++k) {
        float4 wv = *(const float4*)&w_s[k * A_WS_STRIDE + p0];
#pragma unroll
        for (int i = 0; i < 4; ++i) {
            float s = st_s[(r0 + i) * 64 + k];
            acc[i][0] += s * wv.x;
            acc[i][1] += s * wv.y;
            acc[i][2] += s * wv.z;
            acc[i][3] += s * wv.w;
        }
    }

    const float4 bv = *(const float4*)&bias_s[p0];
#pragma unroll
    for (int i = 0; i < 4; ++i) {
        int row = rowBase + r0 + i;
        float4 v;
        v.x = acc[i][0] + bv.x;
        v.y = acc[i][1] + bv.y;
        v.z = acc[i][2] + bv.z;
        v.w = acc[i][3] + bv.w;
        *(float4*)&out[(size_t)row * 64 + p0] = v;
    }
}

// ---------------------------------------------------------------------------
extern "C" void kernel_launch(void* const* d_in, const int* in_sizes, int n_in,
                              void* d_out, int out_size)
{
    const float* state = (const float*)d_in[0];
    const float* w_lk = (const float*)d_in[1];
    const float* b_lk = (const float*)d_in[2];
    const float* w_rk = (const float*)d_in[3];
    const float* b_rk = (const float*)d_in[4];
    const float* w_lv = (const float*)d_in[5];
    const float* b_lv = (const float*)d_in[6];
    const float* w_rv = (const float*)d_in[7];
    const float* b_rv = (const float*)d_in[8];
    const float* w_out = (const float*)d_in[9];
    const float* b_out = (const float*)d_in[10];
    float* out = (float*)d_out;

    dim3 gridA(ROWS_TOTAL / 64, 4);   // 2 row-tiles per block
    proj_kernel<<<gridA, 128>>>(
        state, w_lk, b_lk, w_rk, b_rk, w_lv, b_lv, w_rv, b_rv);

    attn_kernel<<<Bc * Hc * (Nc / TXB) * (Nc / YB), 384>>>();

    out_kernel<<<ROWS_TOTAL / 16, 64>>>(w_out, b_out, out);
}

// round 17
// speedup vs baseline: 1.1309x; 1.1309x over previous
#include <cuda_runtime.h>
#include <cuda_bf16.h>
#include <cstdint>

// Problem constants
#define Bc 2
#define Nc 96
#define NNc 9216            // Nc*Nc
#define Dc 64
#define Hc 4
#define DKc 16
#define ROWS_TOTAL 18432    // Bc*NNc

// Scratch (device globals; allocation-free per harness rules)
__device__ float g_proj[4u * Bc * Hc * NNc * DKc];          // 18.9 MB
__device__ float g_rkT[(size_t)Bc * Hc * Nc * DKc * Nc];    // 4.7 MB
__device__ float g_attout[(size_t)ROWS_TOTAL * Dc];         // 4.7 MB

// ---------------- bf16 helpers ----------------
__device__ __forceinline__ uint32_t pack_bf2(float lo, float hi) {
    uint32_t r;
    asm("cvt.rn.bf16x2.f32 %0, %1, %2;" : "=r"(r) : "f"(hi), "f"(lo));
    return r;
}
__device__ __forceinline__ float bfres(float f) {
    return f - __bfloat162float(__float2bfloat16(f));
}

// m16n8k16 row.col f32.bf16.bf16.f32 (base ISA, sm_80+; compiles for compute_103)
#define MMA16816(c, a, b0_, b1_)                                              \
    asm volatile("mma.sync.aligned.m16n8k16.row.col.f32.bf16.bf16.f32 "       \
        "{%0,%1,%2,%3}, {%4,%5,%6,%7}, {%8,%9}, {%0,%1,%2,%3};"               \
        : "+f"((c)[0]), "+f"((c)[1]), "+f"((c)[2]), "+f"((c)[3])              \
        : "r"((a)[0]), "r"((a)[1]), "r"((a)[2]), "r"((a)[3]),                 \
          "r"(b0_), "r"(b1_))

#define XSTR 66   // bf16 per X row (pad kills bank conflicts; even -> u32 ok)
#define WSTR 66   // bf16 per W row

// smem layout (dynamic): Wh | Wl | Xh | Xl (X region overlaid by fp32 stage) | bias
#define SM_WH   0
#define SM_WL   8448
#define SM_X    16896
#define SM_XL   (16896 + 16896)
#define SM_BIAS (16896 + 33792)
#define SM_TOTAL (16896 + 33792 + 256)   // 50944 B

// ---------------------------------------------------------------------------
// MMA core: computes acc[2][8][4] = X(128x64 rows of this block) @ W^T via
// 3-pass bf16 hi/lo.  Caller provides staged smem tiles.
// ---------------------------------------------------------------------------
struct MmaCtx {
    const __nv_bfloat16 *Xh, *Xl, *Wh, *Wl;
};

__device__ __forceinline__ void run_mma(const MmaCtx& cx, int mbase,
                                        int g, int tig, float acc[2][8][4])
{
#pragma unroll
    for (int mt = 0; mt < 2; ++mt)
#pragma unroll
        for (int nt = 0; nt < 8; ++nt)
#pragma unroll
            for (int j = 0; j < 4; ++j) acc[mt][nt][j] = 0.f;

#pragma unroll
    for (int pass = 0; pass < 3; ++pass) {
        const __nv_bfloat16* A  = (pass == 2) ? cx.Xl : cx.Xh;
        const __nv_bfloat16* Bm = (pass == 1) ? cx.Wl : cx.Wh;
#pragma unroll
        for (int s = 0; s < 4; ++s) {
            const int k0 = s * 16 + 2 * tig;
            uint32_t a[2][4];
#pragma unroll
            for (int mt = 0; mt < 2; ++mt) {
                int r = mbase + mt * 16 + g;
                a[mt][0] = *(const uint32_t*)&A[r * XSTR + k0];
                a[mt][1] = *(const uint32_t*)&A[(r + 8) * XSTR + k0];
                a[mt][2] = *(const uint32_t*)&A[r * XSTR + k0 + 8];
                a[mt][3] = *(const uint32_t*)&A[(r + 8) * XSTR + k0 + 8];
            }
#pragma unroll
            for (int nt = 0; nt < 8; ++nt) {
                int n = nt * 8 + g;
                uint32_t b0 = *(const uint32_t*)&Bm[n * WSTR + k0];
                uint32_t b1 = *(const uint32_t*)&Bm[n * WSTR + k0 + 8];
                MMA16816(acc[0][nt], a[0], b0, b1);
                MMA16816(acc[1][nt], a[1], b0, b1);
            }
        }
    }
}

// Stage X (128 rows x 64 f32) + W (64x64 f32) into bf16 hi/lo smem tiles.
__device__ __forceinline__ void stage_inputs(const float* __restrict__ Xsrc,
                                             const float* __restrict__ W,
                                             const float* __restrict__ Bv,
                                             char* smem, int tid)
{
    __nv_bfloat16* Wh = (__nv_bfloat16*)(smem + SM_WH);
    __nv_bfloat16* Wl = (__nv_bfloat16*)(smem + SM_WL);
    uint32_t* XhW = (uint32_t*)(smem + SM_X);
    uint32_t* XlW = (uint32_t*)(smem + SM_XL);
    float* bias_s = (float*)(smem + SM_BIAS);

    for (int idx = tid; idx < 4096; idx += 128) {
        int p = idx >> 6, k = idx & 63;
        float w = W[idx];
        __nv_bfloat16 wh = __float2bfloat16(w);
        Wh[p * WSTR + k] = wh;
        Wl[p * WSTR + k] = __float2bfloat16(w - __bfloat162float(wh));
    }
    if (tid < 64) bias_s[tid] = Bv[tid];

    const float4* src = (const float4*)Xsrc;
#pragma unroll
    for (int i = 0; i < 16; ++i) {
        int t = tid + i * 128;          // 0..2047 float4s
        float4 v = src[t];
        int r = t >> 4, q = t & 15;
        int w0 = r * 33 + q * 2;        // u32 index (XSTR/2 = 33)
        XhW[w0]     = pack_bf2(v.x, v.y);
        XhW[w0 + 1] = pack_bf2(v.z, v.w);
        XlW[w0]     = pack_bf2(bfres(v.x), bfres(v.y));
        XlW[w0 + 1] = pack_bf2(bfres(v.z), bfres(v.w));
    }
}

// ---------------------------------------------------------------------------
// Kernel A: projection via mma.sync bf16 hi/lo.  128 rows x 64 cols / block,
// 128 threads, one projection per blockIdx.y.  proj==1 -> smem-staged
// transpose into g_rkT (stage overlays X tiles after MMA).
// ---------------------------------------------------------------------------
__global__ void __launch_bounds__(128)
proj_mma_kernel(const float* __restrict__ state,
                const float* __restrict__ w_lk, const float* __restrict__ b_lk,
                const float* __restrict__ w_rk, const float* __restrict__ b_rk,
                const float* __restrict__ w_lv, const float* __restrict__ b_lv,
                const float* __restrict__ w_rv, const float* __restrict__ b_rv)
{
    extern __shared__ __align__(16) char smem[];
    float* stage  = (float*)(smem + SM_X);      // overlay, 128*66 f32
    float* bias_s = (float*)(smem + SM_BIAS);

    const int tid = threadIdx.x;
    const int rowBase = blockIdx.x * 128;
    const int proj = blockIdx.y;

    const float* W = (proj == 0) ? w_lk : (proj == 1) ? w_rk
                    : (proj == 2) ? w_lv : w_rv;
    const float* Bv = (proj == 0) ? b_lk : (proj == 1) ? b_rk
                     : (proj == 2) ? b_lv : b_rv;

    stage_inputs(state + (size_t)rowBase * 64, W, Bv, smem, tid);
    __syncthreads();

    const int wid = tid >> 5, lane = tid & 31;
    const int g = lane >> 2, tig = lane & 3;
    const int mbase = wid * 32;

    MmaCtx cx;
    cx.Xh = (const __nv_bfloat16*)(smem + SM_X);
    cx.Xl = (const __nv_bfloat16*)(smem + SM_XL);
    cx.Wh = (const __nv_bfloat16*)(smem + SM_WH);
    cx.Wl = (const __nv_bfloat16*)(smem + SM_WL);

    float acc[2][8][4];
    run_mma(cx, mbase, g, tig, acc);

    const int b = rowBase / NNc;     // 128 | NNc -> no b crossing
    const int idx0 = rowBase - b * NNc;

    if (proj == 1) {
        __syncthreads();             // everyone done reading X tiles
#pragma unroll
        for (int mt = 0; mt < 2; ++mt) {
            int r = mbase + mt * 16 + g;
#pragma unroll
            for (int nt = 0; nt < 8; ++nt) {
                int col = nt * 8 + 2 * tig;
                stage[r * 66 + col]           = acc[mt][nt][0];
                stage[r * 66 + col + 1]       = acc[mt][nt][1];
                stage[(r + 8) * 66 + col]     = acc[mt][nt][2];
                stage[(r + 8) * 66 + col + 1] = acc[mt][nt][3];
            }
        }
        __syncthreads();
        // thread owns global row rowBase+tid; lanes -> consecutive y
        const int idx = idx0 + tid;
        const int a_ = idx / 96, y = idx - a_ * 96;
#pragma unroll 8
        for (int j = 0; j < 64; ++j) {
            int h = j >> 4, d = j & 15;
            size_t off = ((((size_t)(b * Hc + h) * Nc + a_) * DKc + d) * Nc) + y;
            g_rkT[off] = stage[tid * 66 + j] + bias_s[j];
        }
    } else {
#pragma unroll
        for (int mt = 0; mt < 2; ++mt) {
            int r = mbase + mt * 16 + g;
            int idxr = idx0 + r;
#pragma unroll
            for (int nt = 0; nt < 8; ++nt) {
                int col = nt * 8 + 2 * tig;
                int h = col >> 4, d0 = col & 15;
                float bx = bias_s[col], by = bias_s[col + 1];
                size_t off0 = ((size_t)((proj * Bc + b) * Hc + h) * NNc + idxr) * DKc + d0;
                *(float2*)&g_proj[off0] =
                    make_float2(acc[mt][nt][0] + bx, acc[mt][nt][1] + by);
                *(float2*)&g_proj[off0 + 8 * DKc] =
                    make_float2(acc[mt][nt][2] + bx, acc[mt][nt][3] + by);
            }
        }
    }
}

// ---------------------------------------------------------------------------
// Kernel C: output projection via the same MMA core.  Row-major epilogue.
// ---------------------------------------------------------------------------
__global__ void __launch_bounds__(128)
out_mma_kernel(const float* __restrict__ w_out, const float* __restrict__ b_out,
               float* __restrict__ out)
{
    extern __shared__ __align__(16) char smem[];
    float* bias_s = (float*)(smem + SM_BIAS);

    const int tid = threadIdx.x;
    const int rowBase = blockIdx.x * 128;

    stage_inputs(g_attout + (size_t)rowBase * 64, w_out, b_out, smem, tid);
    __syncthreads();

    const int wid = tid >> 5, lane = tid & 31;
    const int g = lane >> 2, tig = lane & 3;
    const int mbase = wid * 32;

    MmaCtx cx;
    cx.Xh = (const __nv_bfloat16*)(smem + SM_X);
    cx.Xl = (const __nv_bfloat16*)(smem + SM_XL);
    cx.Wh = (const __nv_bfloat16*)(smem + SM_WH);
    cx.Wl = (const __nv_bfloat16*)(smem + SM_WL);

    float acc[2][8][4];
    run_mma(cx, mbase, g, tig, acc);

#pragma unroll
    for (int mt = 0; mt < 2; ++mt) {
        size_t row = (size_t)rowBase + mbase + mt * 16 + g;
#pragma unroll
        for (int nt = 0; nt < 8; ++nt) {
            int col = nt * 8 + 2 * tig;
            float bx = bias_s[col], by = bias_s[col + 1];
            *(float2*)&out[row * 64 + col] =
                make_float2(acc[mt][nt][0] + bx, acc[mt][nt][1] + by);
            *(float2*)&out[(row + 8) * 64 + col] =
                make_float2(acc[mt][nt][2] + bx, acc[mt][nt][3] + by);
        }
    }
}

// ---------------------------------------------------------------------------
// Kernel B: streaming edge-attention, no-max softmax (R12/R14 proven, ACH=24).
// ---------------------------------------------------------------------------
#define TXB 6
#define YB  32
#define ACH 24
#define CF4 (TXB * ACH * DKc / 4)   // 576 float4 per lk/lv chunk

__global__ void __launch_bounds__(384, 3)
attn_kernel()
{
    __shared__ __align__(16) float lk_s[TXB * ACH * DKc];   // 2304
    __shared__ __align__(16) float lv_s[TXB * ACH * DKc];   // 2304
    __shared__ __align__(16) float sc_s[TXB * ACH * YB];    // 4608
    float* part = lk_s;
    float* pden = sc_s + 1024;

    const int tid = threadIdx.x;
    const int yt = blockIdx.x % 3;
    const int xt = (blockIdx.x / 3) & 15;
    const int bh = blockIdx.x / 48;
    const int h  = bh % Hc;
    const int b  = bh / Hc;
    const int x0 = xt * TXB;
    const int yb = yt * YB;

    const int slab = NNc * DKc;  // 147456
    const float* lkbase = g_proj + (size_t)((0 * Bc + b) * Hc + h) * slab;
    const float* lvbase = g_proj + (size_t)((2 * Bc + b) * Hc + h) * slab;
    const float* rvbase = g_proj + (size_t)((3 * Bc + b) * Hc + h) * slab;
    const float* rkT    = g_rkT + (size_t)(b * Hc + h) * Nc * DKc * Nc;

    const int wA = tid >> 5;          // 0..11
    const int lA = tid & 31;          // y-lane
    const int as = tid >> 7;          // 0..2
    const int rr = tid & 127;
    const int yl = rr >> 2;           // 0..31
    const int dq = rr & 3;            // 0..3
    const int y  = yb + yl;

    float4 num[TXB];
    float  den[TXB];
#pragma unroll
    for (int t = 0; t < TXB; ++t) { num[t] = make_float4(0,0,0,0); den[t] = 0.f; }

    for (int a0 = 0; a0 < 96; a0 += ACH) {
        __syncthreads();

        for (int i = tid; i < 2 * CF4; i += 384) {
            int arr = i >= CF4;
            int j   = arr ? i - CF4 : i;
            int tx  = j / (ACH * DKc / 4);
            int k   = j - tx * (ACH * DKc / 4);
            const float* src = (arr ? lvbase : lkbase)
                             + (size_t)((x0 + tx) * 96 + a0) * DKc;
            float* dst = (arr ? lv_s : lk_s) + tx * (ACH * DKc);
            ((float4*)dst)[k] = ((const float4*)src)[k];
        }
        __syncthreads();

#pragma unroll
        for (int rep = 0; rep < 2; ++rep) {
            const int al = wA + rep * 12;
            const int a  = a0 + al;
            const float* rkp = rkT + ((size_t)a * DKc) * Nc + yb + lA;
            float ps[TXB];
            {
                float r[8];
#pragma unroll
                for (int d = 0; d < 8; ++d) r[d] = rkp[(size_t)d * Nc];
#pragma unroll
                for (int tx = 0; tx < TXB; ++tx) {
                    const float4* lp = (const float4*)(lk_s + (tx * ACH + al) * DKc);
                    float4 l0 = lp[0], l1 = lp[1];
                    ps[tx] = l0.x * r[0] + l0.y * r[1] + l0.z * r[2] + l0.w * r[3]
                           + l1.x * r[4] + l1.y * r[5] + l1.z * r[6] + l1.w * r[7];
                }
            }
            {
                float r[8];
#pragma unroll
                for (int d = 0; d < 8; ++d) r[d] = rkp[(size_t)(8 + d) * Nc];
#pragma unroll
                for (int tx = 0; tx < TXB; ++tx) {
                    const float4* lp = (const float4*)(lk_s + (tx * ACH + al) * DKc + 8);
                    float4 l2 = lp[0], l3 = lp[1];
                    float s = ps[tx]
                            + l2.x * r[0] + l2.y * r[1] + l2.z * r[2] + l2.w * r[3]
                            + l3.x * r[4] + l3.y * r[5] + l3.z * r[6] + l3.w * r[7];
                    sc_s[(tx * ACH + al) * YB + lA] = __expf(s * 0.25f);
                }
            }
        }
        __syncthreads();

#pragma unroll
        for (int j = 0; j < 8; ++j) {
            const int al = as * 8 + j;
            const int a  = a0 + al;
            float4 rv = *(const float4*)(rvbase + ((size_t)(a * 96 + y)) * DKc + dq * 4);
#pragma unroll
            for (int tx = 0; tx < TXB; ++tx) {
                float e = sc_s[(tx * ACH + al) * YB + yl];
                float4 v = *(const float4*)(lv_s + (tx * ACH + al) * DKc + dq * 4);
                num[tx].x += e * (v.x * rv.x);
                num[tx].y += e * (v.y * rv.y);
                num[tx].z += e * (v.z * rv.z);
                num[tx].w += e * (v.w * rv.w);
                den[tx]   += e;
            }
        }
    }

    __syncthreads();
#pragma unroll
    for (int step = 0; step < 3; ++step) {
        if (as == step) {
            float4* p4 = (float4*)part;
            if (step == 0) {
#pragma unroll
                for (int tx = 0; tx < TXB; ++tx) {
                    p4[(tx * YB + yl) * 4 + dq] = num[tx];
                    if (dq == 0) pden[tx * YB + yl] = den[tx];
                }
            } else {
#pragma unroll
                for (int tx = 0; tx < TXB; ++tx) {
                    float4 c = p4[(tx * YB + yl) * 4 + dq];
                    c.x += num[tx].x; c.y += num[tx].y;
                    c.z += num[tx].z; c.w += num[tx].w;
                    p4[(tx * YB + yl) * 4 + dq] = c;
                    if (dq == 0) pden[tx * YB + yl] += den[tx];
                }
            }
        }
        __syncthreads();
    }

    {
        const float4* p4 = (const float4*)part;
#pragma unroll
        for (int r = 0; r < 2; ++r) {
            int idx = tid + r * 384;
            int dqo = idx & 3;
            int cyl = (idx >> 2) & 31;
            int tx  = idx >> 7;
            float inv = 1.f / pden[tx * YB + cyl];
            float4 o = p4[idx];
            o.x *= inv; o.y *= inv; o.z *= inv; o.w *= inv;
            size_t row = (size_t)b * NNc + (size_t)(x0 + tx) * 96 + (yb + cyl);
            *(float4*)&g_attout[row * 64 + h * 16 + dqo * 4] = o;
        }
    }
}

// ---------------------------------------------------------------------------
extern "C" void kernel_launch(void* const* d_in, const int* in_sizes, int n_in,
                              void* d_out, int out_size)
{
    const float* state = (const float*)d_in[0];
    const float* w_lk = (const float*)d_in[1];
    const float* b_lk = (const float*)d_in[2];
    const float* w_rk = (const float*)d_in[3];
    const float* b_rk = (const float*)d_in[4];
    const float* w_lv = (const float*)d_in[5];
    const float* b_lv = (const float*)d_in[6];
    const float* w_rv = (const float*)d_in[7];
    const float* b_rv = (const float*)d_in[8];
    const float* w_out = (const float*)d_in[9];
    const float* b_out = (const float*)d_in[10];
    float* out = (float*)d_out;

    static bool attr_done = false;
    if (!attr_done) {
        cudaFuncSetAttribute(proj_mma_kernel,
                             cudaFuncAttributeMaxDynamicSharedMemorySize, SM_TOTAL);
        cudaFuncSetAttribute(out_mma_kernel,
                             cudaFuncAttributeMaxDynamicSharedMemorySize, SM_TOTAL);
        attr_done = true;
    }

    dim3 gridA(ROWS_TOTAL / 128, 4);
    proj_mma_kernel<<<gridA, 128, SM_TOTAL>>>(
        state, w_lk, b_lk, w_rk, b_rk, w_lv, b_lv, w_rv, b_rv);

    attn_kernel<<<Bc * Hc * (Nc / TXB) * (Nc / YB), 384>>>();

    out_mma_kernel<<<ROWS_TOTAL / 128, 128, SM_TOTAL>>>(w_out, b_out, out);
}